// round 9
// baseline (speedup 1.0000x reference)
#include <cuda_runtime.h>
#include <cstdint>
#include <cstddef>

#define BB 32
#define TT 128
#define LL 64
#define HH 512
#define AA 256
#define DD 512
#define NCOL 2048
#define NBLK 144
#define NTH 512

typedef unsigned long long u64;

// ---------------- device scratch ----------------
__device__ float g_xg[(size_t)TT * BB * NCOL];     // [t*32+b][col]
__device__ float g_ctr[(size_t)BB * LL * AA];      // ctx_trans [b*64+l][a]
__device__ float g_ctxC[(size_t)BB * LL * NCOL];   // context@C [b*64+l][col]
__device__ float g_attv[(size_t)BB * AA];          // [b][a]
__device__ float g_apr[(size_t)BB * 32 * 2];       // softmax-weight pairs [b][l2]{e,o}
__device__ float g_hb0[(size_t)256 * BB * 2];      // h pair buffers [k2][b]{e,o}
__device__ float g_hb1[(size_t)256 * BB * 2];
__device__ float g_zbias[512];
__device__ unsigned g_fatt[16 * 32];
__device__ unsigned g_fscore[16 * 32];
__device__ unsigned g_fcol[128 * 32];
__device__ unsigned g_epoch;

// ---------------- helpers ----------------
__device__ __forceinline__ u64 pk2(float lo, float hi) {
    u64 r; asm("mov.b64 %0, {%1,%2};" : "=l"(r) : "f"(lo), "f"(hi)); return r;
}
__device__ __forceinline__ float2 upk2(u64 v) {
    float2 r; asm("mov.b64 {%0,%1}, %2;" : "=f"(r.x), "=f"(r.y) : "l"(v)); return r;
}
__device__ __forceinline__ u64 fma2(u64 a, u64 b, u64 c) {
    u64 d; asm("fma.rn.f32x2 %0, %1, %2, %3;" : "=l"(d) : "l"(a), "l"(b), "l"(c)); return d;
}
__device__ __forceinline__ float tanh_ap(float x) {
    float y; asm("tanh.approx.f32 %0, %1;" : "=f"(y) : "f"(x)); return y;
}
__device__ __forceinline__ float sig_ap(float x) {
    return fmaf(tanh_ap(0.5f * x), 0.5f, 0.5f);
}

// ---------------- prologue GEMM, f32x2 inner product ----------------
__global__ void __launch_bounds__(256) gemm_proj(
    const float* __restrict__ A,
    const float* __restrict__ Wa, const float* __restrict__ Wb,
    const float* __restrict__ Wc, const float* __restrict__ Wd,
    const float* __restrict__ ba, const float* __restrict__ bbi,
    const float* __restrict__ bc, const float* __restrict__ bd,
    float* __restrict__ Out, int Ncols, int wN, int wstride, int tb_mode)
{
    __shared__ u64 As2[8][64];
    __shared__ u64 Bs2[8][64];
    int tid = threadIdx.x;
    int ntile = blockIdx.x, mtile = blockIdx.y;

    int gate = (ntile * 64) / 512;
    const float* Wsel = (gate == 0) ? Wa : (gate == 1) ? Wb : (gate == 2) ? Wc : Wd;
    const float* bsel = (gate == 0) ? ba : (gate == 1) ? bbi : (gate == 2) ? bc : bd;
    int ncolbase = (ntile * 64) % wN;

    int a_r = tid >> 2;
    int a_k = (tid & 3) * 4;
    int grow = mtile * 64 + a_r;
    const float* aptr;
    if (tb_mode) {
        int t = grow >> 5, b = grow & 31;
        aptr = A + ((size_t)(b * TT + t)) * DD;
    } else {
        aptr = A + (size_t)grow * DD;
    }
    int bl_k2 = (tid >> 4) & 7;
    int bl_n  = (tid & 15) * 4;
    bool bldr = tid < 128;

    int tx = tid & 15, ty = tid >> 4;
    u64 acc2[4][4];
#pragma unroll
    for (int i = 0; i < 4; i++)
#pragma unroll
        for (int j = 0; j < 4; j++) acc2[i][j] = 0;

    for (int k0 = 0; k0 < DD; k0 += 16) {
        float4 av = *(const float4*)(aptr + k0 + a_k);
        float4 b0, b1;
        if (bldr) {
            b0 = *(const float4*)(Wsel + (size_t)(k0 + 2 * bl_k2) * wstride + ncolbase + bl_n);
            b1 = *(const float4*)(Wsel + (size_t)(k0 + 2 * bl_k2 + 1) * wstride + ncolbase + bl_n);
        }
        __syncthreads();
        As2[(a_k >> 1)][a_r]     = pk2(av.x, av.y);
        As2[(a_k >> 1) + 1][a_r] = pk2(av.z, av.w);
        if (bldr) {
            Bs2[bl_k2][bl_n + 0] = pk2(b0.x, b1.x);
            Bs2[bl_k2][bl_n + 1] = pk2(b0.y, b1.y);
            Bs2[bl_k2][bl_n + 2] = pk2(b0.z, b1.z);
            Bs2[bl_k2][bl_n + 3] = pk2(b0.w, b1.w);
        }
        __syncthreads();
#pragma unroll
        for (int k2 = 0; k2 < 8; k2++) {
            ulonglong2 a01 = *(const ulonglong2*)&As2[k2][ty * 4];
            ulonglong2 a23 = *(const ulonglong2*)&As2[k2][ty * 4 + 2];
            ulonglong2 b01 = *(const ulonglong2*)&Bs2[k2][tx * 4];
            ulonglong2 b23 = *(const ulonglong2*)&Bs2[k2][tx * 4 + 2];
            u64 aa[4] = {a01.x, a01.y, a23.x, a23.y};
            u64 bb4[4] = {b01.x, b01.y, b23.x, b23.y};
#pragma unroll
            for (int i = 0; i < 4; i++)
#pragma unroll
                for (int j = 0; j < 4; j++) acc2[i][j] = fma2(aa[i], bb4[j], acc2[i][j]);
        }
    }
#pragma unroll
    for (int i = 0; i < 4; i++) {
        int gr = mtile * 64 + ty * 4 + i;
        float r[4];
#pragma unroll
        for (int j = 0; j < 4; j++) {
            float2 v = upk2(acc2[i][j]);
            r[j] = v.x + v.y + bsel[(ncolbase + tx * 4 + j) % wN];
        }
        *(float4*)(Out + (size_t)gr * Ncols + ntile * 64 + tx * 4) =
            make_float4(r[0], r[1], r[2], r[3]);
    }
}

// smem map (floats)
#define OFF_H    8192
#define OFF_BIG  16384
#define OFF_APR  49152
#define OFF_RED  51200
#define OFF_ACC  52224
#define OFF_DOT  52736
#define OFF_CST  53248
#define OFF_HST  53376
#define OFF_AUX  53504
#define OFF_W2   54016
#define OFF_E    54272
#define OFF_A    54400
#define OFF_SUM  54528
#define SMEM_FLOATS 54536

// ---------------- persistent recurrent kernel ----------------
__global__ void __launch_bounds__(NTH, 1) recur_kernel(
    const float* __restrict__ context,
    const float* __restrict__ mask,
    const int*   __restrict__ cmask,
    const float* __restrict__ U0, const float* __restrict__ U1,
    const float* __restrict__ U2, const float* __restrict__ U3,
    const float* __restrict__ W1h,
    const float* __restrict__ W2, const float* __restrict__ b2,
    float* __restrict__ out)
{
    extern __shared__ float smem[];
    u64*   sW64  = (u64*)smem;                     // 4096 u64 weight slice
    float* sH    = smem + OFF_H;                   // h half-buffer
    u64*   sH64  = (u64*)sH;
    float* sBIG  = smem + OFF_BIG;                 // col: ctxC pairs; att: ctr
    u64*   sCtxC64 = (u64*)sBIG;
    float* sApr  = smem + OFF_APR;                 // col: apr pairs; att: out_x partials
    u64*   sApr64 = (u64*)sApr;
    float* sRed  = smem + OFF_RED;                 // 1024
    float* sAcc  = smem + OFF_ACC;                 // 512
    float* sDot  = smem + OFF_DOT;                 // 512
    float* sCst  = smem + OFF_CST;                 // 128
    float* sHst  = smem + OFF_HST;                 // 128
    float* sAux  = smem + OFF_AUX;                 // att: attv 512
    float* sW2s  = smem + OFF_W2;                  // 256
    float* sE    = smem + OFF_E;                   // 128
    float* sA    = smem + OFF_A;                   // 128
    float* sSum  = smem + OFF_SUM;

    const int tid = threadIdx.x;
    const int bid = blockIdx.x;
    const bool isCol = (bid < 128);
    float* out_h = out;
    float* out_c = out + (size_t)BB * TT * HH;
    float* out_x = out + (size_t)2 * BB * TT * HH;
    const float b2v = b2[0];

    unsigned base = *(volatile unsigned*)&g_epoch;

    // P1 thread roles
    const int colL = tid & 15;
    const int bq   = (tid >> 4) & 7;
    const int kq   = tid >> 7;
    const int ch0  = bid * 4;           // col-blocks
    const int ab   = bid - 128;         // att-blocks
    const int sb0  = ab * 2;            // scorer batches

    // ---- startup: weight slice into SMEM ----
    for (int idx = tid; idx < 4096; idx += NTH) {
        int k2 = idx >> 4, ci = idx & 15;
        float e, o;
        if (isCol) {
            int g = ci >> 2, ch = ch0 + (ci & 3);
            const float* Ug = (g == 0) ? U0 : (g == 1) ? U1 : (g == 2) ? U2 : U3;
            e = Ug[(size_t)(2 * k2) * 512 + ch];
            o = Ug[(size_t)(2 * k2 + 1) * 512 + ch];
        } else {
            int a = ab * 16 + ci;
            e = W1h[(size_t)(2 * k2) * AA + a];
            o = W1h[(size_t)(2 * k2 + 1) * AA + a];
        }
        sW64[idx] = pk2(e, o);
    }
    // ---- startup: big persistent slice ----
    if (isCol) {
        // ctxC pairs over l: sCtxC64[(b*32+l2)*16 + ci]
        for (int idx = tid; idx < 16384; idx += NTH) {
            int ci = idx & 15;
            int r = idx >> 4;
            int b = r >> 5, l2 = r & 31;
            int gcol = (ci >> 2) * 512 + ch0 + (ci & 3);
            float e = g_ctxC[((size_t)(b * 64 + 2 * l2)) * NCOL + gcol];
            float o = g_ctxC[((size_t)(b * 64 + 2 * l2 + 1)) * NCOL + gcol];
            sCtxC64[idx] = pk2(e, o);
        }
    } else {
        // ctr for batches sb0, sb0+1 (contiguous 32768 floats)
        const float4* src = (const float4*)(g_ctr + (size_t)sb0 * LL * AA);
        float4* dst = (float4*)sBIG;
        for (int f4 = tid; f4 < 8192; f4 += NTH) dst[f4] = src[f4];
    }
    if (tid < AA) sW2s[tid] = W2[tid];
    // zero local state
    if (tid < 128) { sCst[tid] = 0.f; sHst[tid] = 0.f; }
    __syncthreads();

    for (int t = 0; t < TT; t++) {
        const unsigned gen = base + (unsigned)(t + 1);
        const float* hread = (t & 1) ? g_hb1 : g_hb0;
        float* hwrite = (t & 1) ? g_hb0 : g_hb1;

        // xg prefetch (col, kq==0 reducer threads)
        float xgv[4];
        if (isCol && kq == 0) {
            int gcol = (colL >> 2) * 512 + ch0 + (colL & 3);
#pragma unroll
            for (int bi = 0; bi < 4; bi++) {
                int b = bq * 4 + bi;
                xgv[bi] = g_xg[((size_t)(t * 32 + b)) * NCOL + gcol];
            }
        }

        // ===== P1: matvec over h (two 32KB halves) =====
        u64 ac[4] = {0, 0, 0, 0};
#pragma unroll 1
        for (int half = 0; half < 2; half++) {
            {
                float4* dst = (float4*)sH;
                if (t == 0) {
                    for (int f4 = tid; f4 < 2048; f4 += NTH)
                        dst[f4] = make_float4(0.f, 0.f, 0.f, 0.f);
                } else {
                    const float4* src = (const float4*)hread;
                    for (int f4 = tid; f4 < 2048; f4 += NTH)
                        dst[f4] = src[half * 2048 + f4];
                }
            }
            __syncthreads();
            if (t > 0) {
                const u64* wp = sW64 + ((half * 128 + kq * 32) * 16) + colL;
                const u64* hp = sH64 + (kq * 32) * 32 + bq * 4;
#pragma unroll 8
                for (int p = 0; p < 32; p++) {
                    u64 w = *wp;
                    ulonglong2 ha = *(const ulonglong2*)hp;
                    ulonglong2 hb = *(const ulonglong2*)(hp + 2);
                    ac[0] = fma2(w, ha.x, ac[0]);
                    ac[1] = fma2(w, ha.y, ac[1]);
                    ac[2] = fma2(w, hb.x, ac[2]);
                    ac[3] = fma2(w, hb.y, ac[3]);
                    wp += 16; hp += 32;
                }
            }
            __syncthreads();
        }
        // reduce 4 kq partials
        float part[4];
#pragma unroll
        for (int bi = 0; bi < 4; bi++) {
            float2 r = upk2(ac[bi]);
            part[bi] = r.x + r.y;
        }
        {
            int idx0 = (bq * 4) * 16 + colL;
            if (kq == 1) {
#pragma unroll
                for (int bi = 0; bi < 4; bi++) sRed[idx0 + bi * 16] = part[bi];
            } else if (kq == 3) {
#pragma unroll
                for (int bi = 0; bi < 4; bi++) sRed[512 + idx0 + bi * 16] = part[bi];
            }
            __syncthreads();
            if (kq == 0) {
#pragma unroll
                for (int bi = 0; bi < 4; bi++) part[bi] += sRed[idx0 + bi * 16];
            } else if (kq == 2) {
#pragma unroll
                for (int bi = 0; bi < 4; bi++)
                    sRed[512 + idx0 + bi * 16] += part[bi];
            }
            __syncthreads();
            if (kq == 0) {
                if (isCol) {
#pragma unroll
                    for (int bi = 0; bi < 4; bi++) {
                        float tot = part[bi] + sRed[512 + idx0 + bi * 16] + xgv[bi];
                        sAcc[colL * 32 + bq * 4 + bi] = tot;
                    }
                } else {
#pragma unroll
                    for (int bi = 0; bi < 4; bi++) {
                        float tot = part[bi] + sRed[512 + idx0 + bi * 16];
                        int b = bq * 4 + bi;
                        g_attv[b * AA + ab * 16 + colL] = tot;
                    }
                    __threadfence();
                }
            }
        }
        __syncthreads();

        if (!isCol) {
            // ===== att/scorer block =====
            if (tid == 0)
                *(volatile unsigned*)&g_fatt[ab * 32] = gen;
            if (tid < 16) {
                while (*(volatile unsigned*)&g_fatt[tid * 32] < gen) { }
            }
            __syncthreads();
            if (tid == 0) __threadfence();   // L1 inval: see other blocks' attv
            __syncthreads();
            // load attv for my 2 batches (contiguous 512 floats)
            sAux[tid] = g_attv[sb0 * AA + tid];
            __syncthreads();
            // scores
            {
                int warp = tid >> 5, lane = tid & 31;
                int bsel = warp >> 3;
                int lbase = (warp & 7) * 8;
                const float* ctb = sBIG + bsel * 16384;
                const float* avb = sAux + bsel * 256;
#pragma unroll
                for (int i = 0; i < 8; i++) {
                    int l = lbase + i;
                    const float* ct = ctb + l * 256;
                    float p = 0.f;
#pragma unroll
                    for (int j = 0; j < 8; j++) {
                        int a = lane + j * 32;
                        p += tanh_ap(ct[a] + avb[a]) * sW2s[a];
                    }
#pragma unroll
                    for (int o = 16; o > 0; o >>= 1) p += __shfl_xor_sync(0xffffffffu, p, o);
                    if (lane == 0)
                        sE[bsel * 64 + l] = __expf(p + b2v) *
                                            (float)cmask[(sb0 + bsel) * LL + l];
                }
            }
            __syncthreads();
            if (tid < 64) {
                int bsel2 = tid >> 5, lane = tid & 31;
                float v = sE[bsel2 * 64 + lane] + sE[bsel2 * 64 + 32 + lane];
#pragma unroll
                for (int o = 16; o > 0; o >>= 1) v += __shfl_xor_sync(0xffffffffu, v, o);
                if (lane == 0) sSum[bsel2] = v;
            }
            __syncthreads();
            if (tid < 128) {
                int bsel2 = tid >> 6;
                sA[tid] = sE[tid] * __fdividef(1.0f, sSum[bsel2]);
            }
            __syncthreads();
            // write softmax-weight pairs
            if (tid < 64) {
                int bsel2 = tid >> 5, l2 = tid & 31;
                u64 pr = pk2(sA[bsel2 * 64 + 2 * l2], sA[bsel2 * 64 + 2 * l2 + 1]);
                *(u64*)&g_apr[((size_t)(sb0 + bsel2) * 32 + l2) * 2] = pr;
            }
            // out_x: thread (bsel, lg, d4)
            {
                int bsel2 = tid >> 8;
                int lg = (tid >> 7) & 1;
                int d4 = tid & 127;
                float4 xp = make_float4(0.f, 0.f, 0.f, 0.f);
                const float* cb = context +
                    ((size_t)(sb0 + bsel2) * LL + lg * 32) * DD + d4 * 4;
                const float* ap = sA + bsel2 * 64 + lg * 32;
#pragma unroll 4
                for (int li = 0; li < 32; li++) {
                    float av = ap[li];
                    float4 v = *(const float4*)(cb + (size_t)li * DD);
                    xp.x += av * v.x; xp.y += av * v.y;
                    xp.z += av * v.z; xp.w += av * v.w;
                }
                ((float4*)sApr)[tid] = xp;
                __syncthreads();
                if (lg == 0) {
                    float4 v2 = ((float4*)sApr)[tid + 128];
                    xp.x += v2.x; xp.y += v2.y; xp.z += v2.z; xp.w += v2.w;
                    *(float4*)(out_x + ((size_t)(sb0 + bsel2) * TT + t) * DD + d4 * 4) = xp;
                    __threadfence();
                }
            }
            __syncthreads();
            if (tid == 0)
                *(volatile unsigned*)&g_fscore[ab * 32] = gen;
        } else {
            // ===== col block: wait for softmax weights =====
            if (tid < 16) {
                while (*(volatile unsigned*)&g_fscore[tid * 32] < gen) { }
            }
            __syncthreads();
            if (tid == 0) __threadfence();   // L1 inval: see apr
            __syncthreads();
            // load apr pairs (1024 u64 = 512 float4)
            ((float4*)sApr)[tid] = ((const float4*)g_apr)[tid];
            __syncthreads();
            // ctxC dot: thread (ci, b)
            {
                int ci = tid & 15, bb = tid >> 4;
                const u64* cp = sCtxC64 + bb * 32 * 16 + ci;
                const u64* ap = sApr64 + bb * 32;
                u64 acc = 0;
#pragma unroll 8
                for (int l2 = 0; l2 < 32; l2++)
                    acc = fma2(cp[l2 * 16], ap[l2], acc);
                float2 r = upk2(acc);
                sDot[ci * 32 + bb] = r.x + r.y;
            }
            __syncthreads();
            // fused LSTM epilogue: 64 threads, each (b, ch-pair)
            if (tid < 64) {
                int bb = tid & 31, j = tid >> 5;
                float m = mask[bb * TT + t];
                float hn2[2], cn2[2];
#pragma unroll
                for (int pp = 0; pp < 2; pp++) {
                    int chI = 2 * j + pp;
                    float gs[4];
#pragma unroll
                    for (int g = 0; g < 4; g++) {
                        int ci = g * 4 + chI;
                        gs[g] = sAcc[ci * 32 + bb] + sDot[ci * 32 + bb];
                    }
                    float cprev = sCst[chI * 32 + bb];
                    float hprev = sHst[chI * 32 + bb];
                    float iv = sig_ap(gs[0]);
                    float fv = sig_ap(gs[1]);
                    float gv = tanh_ap(gs[2]);
                    float ov = sig_ap(gs[3]);
                    float cn = fv * cprev + iv * gv;
                    float hn = ov * tanh_ap(cn);
                    hn = (1.f - m) * hprev + m * hn;
                    cn = (1.f - m) * cprev + m * cn;
                    sCst[chI * 32 + bb] = cn;
                    sHst[chI * 32 + bb] = hn;
                    hn2[pp] = hn; cn2[pp] = cn;
                }
                int ch = ch0 + 2 * j;
                *(float2*)(out_h + ((size_t)bb * TT + t) * HH + ch) =
                    make_float2(hn2[0], hn2[1]);
                *(float2*)(out_c + ((size_t)bb * TT + t) * HH + ch) =
                    make_float2(cn2[0], cn2[1]);
                *(u64*)&hwrite[((size_t)(ch >> 1) * 32 + bb) * 2] = pk2(hn2[0], hn2[1]);
                __threadfence();
            }
            __syncthreads();
            if (tid == 0)
                *(volatile unsigned*)&g_fcol[bid * 32] = gen;
        }

        // ===== full barrier on col flags =====
        if (tid < 128) {
            while (*(volatile unsigned*)&g_fcol[tid * 32] < gen) { }
        }
        __syncthreads();
        if (tid == 0) __threadfence();
        __syncthreads();
    }

    if (bid == 0 && tid == 0)
        *(volatile unsigned*)&g_epoch = base + (unsigned)TT;
}

// ---------------- host launcher ----------------
extern "C" void kernel_launch(void* const* d_in, const int* in_sizes, int n_in,
                              void* d_out, int out_size) {
    (void)in_sizes; (void)n_in; (void)out_size;
    const float* X    = (const float*)d_in[0];
    const float* ctx  = (const float*)d_in[1];
    const float* mask = (const float*)d_in[2];
    const int*   cm   = (const int*)d_in[3];
    const float* W[4]; const float* U[4]; const float* C[4]; const float* bi[4];
    for (int gg = 0; gg < 4; gg++) {
        W[gg]  = (const float*)d_in[4 + 4 * gg];
        U[gg]  = (const float*)d_in[5 + 4 * gg];
        C[gg]  = (const float*)d_in[6 + 4 * gg];
        bi[gg] = (const float*)d_in[7 + 4 * gg];
    }
    const float* attW1c = (const float*)d_in[20];
    const float* attW1h = (const float*)d_in[21];
    const float* attB1  = (const float*)d_in[22];
    const float* attW2  = (const float*)d_in[23];
    const float* attB2  = (const float*)d_in[24];
    float* out = (float*)d_out;

    float *xg_ptr = nullptr, *ctr_ptr = nullptr, *ctxC_ptr = nullptr, *zb_ptr = nullptr;
    cudaGetSymbolAddress((void**)&xg_ptr, g_xg);
    cudaGetSymbolAddress((void**)&ctr_ptr, g_ctr);
    cudaGetSymbolAddress((void**)&ctxC_ptr, g_ctxC);
    cudaGetSymbolAddress((void**)&zb_ptr, g_zbias);

    // xg = X@W + b : rows (t*32+b), cols 2048
    dim3 grid1(NCOL / 64, (TT * BB) / 64);
    gemm_proj<<<grid1, 256>>>(X, W[0], W[1], W[2], W[3],
                              bi[0], bi[1], bi[2], bi[3],
                              xg_ptr, NCOL, 512, 512, 1);
    // ctx_trans = context@att_ctx_W1 + b1
    dim3 grid2(AA / 64, (BB * LL) / 64);
    gemm_proj<<<grid2, 256>>>(ctx, attW1c, attW1c, attW1c, attW1c,
                              attB1, attB1, attB1, attB1,
                              ctr_ptr, AA, AA, AA, 0);
    // ctxC = context@C
    dim3 grid3(NCOL / 64, (BB * LL) / 64);
    gemm_proj<<<grid3, 256>>>(ctx, C[0], C[1], C[2], C[3],
                              zb_ptr, zb_ptr, zb_ptr, zb_ptr,
                              ctxC_ptr, NCOL, 512, 512, 0);

    size_t smem_bytes = (size_t)SMEM_FLOATS * sizeof(float);
    static bool attr_set = false;
    if (!attr_set) {
        cudaFuncSetAttribute(recur_kernel, cudaFuncAttributeMaxDynamicSharedMemorySize,
                             (int)smem_bytes);
        attr_set = true;
    }
    recur_kernel<<<NBLK, NTH, smem_bytes>>>(ctx, mask, cm,
                                            U[0], U[1], U[2], U[3], attW1h,
                                            attW2, attB2, out);
}

// round 10
// speedup vs baseline: 1.3852x; 1.3852x over previous
#include <cuda_runtime.h>
#include <cstdint>
#include <cstddef>

#define BB 32
#define TT 128
#define LL 64
#define HH 512
#define AA 256
#define DD 512
#define NCOL 2048
#define UCOLS 2304
#define NBLK 144
#define NTH 512
#define QCH 128

typedef unsigned long long u64;

// ---------------- device scratch ----------------
__device__ float g_xg[(size_t)TT * BB * NCOL];     // [t*32+b][col]
__device__ float g_ctr[(size_t)BB * LL * AA];      // ctx_trans [b*64+l][a]
__device__ float g_ctxC[(size_t)BB * LL * NCOL];   // context@C [b*64+l][col]
__device__ float g_gbuf[(size_t)BB * NCOL];        // [b][col]
__device__ float g_attv[(size_t)BB * AA];          // [b][a]
__device__ float g_hp[(size_t)256 * BB * 2];       // h pairs [k2][b]{e,o}
__device__ float g_cst[(size_t)BB * HH];           // c state [b][ch]
__device__ float g_zbias[512];
__device__ unsigned g_arr[NBLK * 32];              // arrival flags, 128B apart
__device__ unsigned g_epoch;

// ---------------- helpers ----------------
__device__ __forceinline__ u64 pk2(float lo, float hi) {
    u64 r; asm("mov.b64 %0, {%1,%2};" : "=l"(r) : "f"(lo), "f"(hi)); return r;
}
__device__ __forceinline__ float2 upk2(u64 v) {
    float2 r; asm("mov.b64 {%0,%1}, %2;" : "=f"(r.x), "=f"(r.y) : "l"(v)); return r;
}
__device__ __forceinline__ u64 fma2(u64 a, u64 b, u64 c) {
    u64 d; asm("fma.rn.f32x2 %0, %1, %2, %3;" : "=l"(d) : "l"(a), "l"(b), "l"(c)); return d;
}
__device__ __forceinline__ u64 add2(u64 a, u64 b) {
    u64 d; asm("add.rn.f32x2 %0, %1, %2;" : "=l"(d) : "l"(a), "l"(b)); return d;
}
__device__ __forceinline__ float tanh_ap(float x) {
    float y; asm("tanh.approx.f32 %0, %1;" : "=f"(y) : "f"(x)); return y;
}
__device__ __forceinline__ float sig_ap(float x) {
    return fmaf(tanh_ap(0.5f * x), 0.5f, 0.5f);
}
__device__ __forceinline__ void st_release(unsigned* p, unsigned v) {
    asm volatile("st.release.gpu.global.u32 [%0], %1;" :: "l"(p), "r"(v) : "memory");
}
__device__ __forceinline__ unsigned ld_acquire(const unsigned* p) {
    unsigned v;
    asm volatile("ld.acquire.gpu.global.u32 %0, [%1];" : "=r"(v) : "l"(p) : "memory");
    return v;
}

// grid barrier with scoped release/acquire — NO full fence, NO L1 flush.
// release orders all prior global stores; acquire loads synchronize-with it.
// Cross-block mutable data is read post-barrier via __ldcg (L2-direct), so
// stale L1 lines can never be observed.
__device__ __forceinline__ void gbar(int bid, int tid, unsigned gen) {
    __syncthreads();
    if (tid == 0) st_release(&g_arr[bid * 32], gen);
    if (tid < NBLK) {
        while (ld_acquire(&g_arr[tid * 32]) < gen) { }
    }
    __syncthreads();
}

// ---------------- prologue GEMM, f32x2 inner product ----------------
__global__ void __launch_bounds__(256) gemm_proj(
    const float* __restrict__ A,
    const float* __restrict__ Wa, const float* __restrict__ Wb,
    const float* __restrict__ Wc, const float* __restrict__ Wd,
    const float* __restrict__ ba, const float* __restrict__ bbi,
    const float* __restrict__ bc, const float* __restrict__ bd,
    float* __restrict__ Out, int Ncols, int wN, int wstride, int tb_mode)
{
    __shared__ u64 As2[8][64];
    __shared__ u64 Bs2[8][64];
    int tid = threadIdx.x;
    int ntile = blockIdx.x, mtile = blockIdx.y;

    int gate = (ntile * 64) / 512;
    const float* Wsel = (gate == 0) ? Wa : (gate == 1) ? Wb : (gate == 2) ? Wc : Wd;
    const float* bsel = (gate == 0) ? ba : (gate == 1) ? bbi : (gate == 2) ? bc : bd;
    int ncolbase = (ntile * 64) % wN;

    int a_r = tid >> 2;
    int a_k = (tid & 3) * 4;
    int grow = mtile * 64 + a_r;
    const float* aptr;
    if (tb_mode) {
        int t = grow >> 5, b = grow & 31;
        aptr = A + ((size_t)(b * TT + t)) * DD;
    } else {
        aptr = A + (size_t)grow * DD;
    }
    int bl_k2 = (tid >> 4) & 7;
    int bl_n  = (tid & 15) * 4;
    bool bldr = tid < 128;

    int tx = tid & 15, ty = tid >> 4;
    u64 acc2[4][4];
#pragma unroll
    for (int i = 0; i < 4; i++)
#pragma unroll
        for (int j = 0; j < 4; j++) acc2[i][j] = 0;

    for (int k0 = 0; k0 < DD; k0 += 16) {
        float4 av = *(const float4*)(aptr + k0 + a_k);
        float4 b0, b1;
        if (bldr) {
            b0 = *(const float4*)(Wsel + (size_t)(k0 + 2 * bl_k2) * wstride + ncolbase + bl_n);
            b1 = *(const float4*)(Wsel + (size_t)(k0 + 2 * bl_k2 + 1) * wstride + ncolbase + bl_n);
        }
        __syncthreads();
        As2[(a_k >> 1)][a_r]     = pk2(av.x, av.y);
        As2[(a_k >> 1) + 1][a_r] = pk2(av.z, av.w);
        if (bldr) {
            Bs2[bl_k2][bl_n + 0] = pk2(b0.x, b1.x);
            Bs2[bl_k2][bl_n + 1] = pk2(b0.y, b1.y);
            Bs2[bl_k2][bl_n + 2] = pk2(b0.z, b1.z);
            Bs2[bl_k2][bl_n + 3] = pk2(b0.w, b1.w);
        }
        __syncthreads();
#pragma unroll
        for (int k2 = 0; k2 < 8; k2++) {
            ulonglong2 a01 = *(const ulonglong2*)&As2[k2][ty * 4];
            ulonglong2 a23 = *(const ulonglong2*)&As2[k2][ty * 4 + 2];
            ulonglong2 b01 = *(const ulonglong2*)&Bs2[k2][tx * 4];
            ulonglong2 b23 = *(const ulonglong2*)&Bs2[k2][tx * 4 + 2];
            u64 aa[4] = {a01.x, a01.y, a23.x, a23.y};
            u64 bb4[4] = {b01.x, b01.y, b23.x, b23.y};
#pragma unroll
            for (int i = 0; i < 4; i++)
#pragma unroll
                for (int j = 0; j < 4; j++) acc2[i][j] = fma2(aa[i], bb4[j], acc2[i][j]);
        }
    }
#pragma unroll
    for (int i = 0; i < 4; i++) {
        int gr = mtile * 64 + ty * 4 + i;
        float r[4];
#pragma unroll
        for (int j = 0; j < 4; j++) {
            float2 v = upk2(acc2[i][j]);
            r[j] = v.x + v.y + bsel[(ncolbase + tx * 4 + j) % wN];
        }
        *(float4*)(Out + (size_t)gr * Ncols + ntile * 64 + tx * 4) =
            make_float4(r[0], r[1], r[2], r[3]);
    }
}

// smem map (floats):
//   sW   [0, 8192)        : 4096 u64 = persistent weight slice [k2][16 cols]
//   sTp  [8192, 24576)    : 8192 u64 = h pairs [k2][32 b]
//   sRed [24576, 26624)   : P1 k-partials (4x512); P2 out_x partials + sRedU
//   aux  [26624, 27912)
#define OFF_TP    8192
#define OFF_RED   24576
#define OFF_ATT   26624
#define OFF_W2    26880
#define OFF_E     27136
#define OFF_A     27200
#define OFF_APAIR 27264
#define OFF_G     27392
#define OFF_SUM   27904
#define SMEM_FLOATS 27912

// ---------------- persistent recurrent kernel ----------------
__global__ void __launch_bounds__(NTH, 1) recur_kernel(
    const float* __restrict__ context,
    const float* __restrict__ mask,
    const int*   __restrict__ cmask,
    const float* __restrict__ U0, const float* __restrict__ U1,
    const float* __restrict__ U2, const float* __restrict__ U3,
    const float* __restrict__ W1h,
    const float* __restrict__ W2, const float* __restrict__ b2,
    float* __restrict__ out)
{
    extern __shared__ float smem[];
    u64*   sW64  = (u64*)smem;
    float* sTp   = smem + OFF_TP;
    u64*   sTp64 = (u64*)sTp;
    float* sRed  = smem + OFF_RED;
    u64*   sRedU = (u64*)(sRed + 1536);   // 256 u64
    float* sAtt  = smem + OFF_ATT;
    float* sW2s  = smem + OFF_W2;
    float* sE    = smem + OFF_E;
    float* sA    = smem + OFF_A;
    u64*   sApr  = (u64*)(smem + OFF_APAIR);
    float* sG    = smem + OFF_G;
    float* sSum  = smem + OFF_SUM;

    const int tid = threadIdx.x;
    const int bid = blockIdx.x;
    float* out_h = out;
    float* out_c = out + (size_t)BB * TT * HH;
    float* out_x = out + (size_t)2 * BB * TT * HH;
    const float b2v = b2[0];

    unsigned base = ld_acquire(&g_epoch);

    // P1 roles: thread = colL(16) x bq(8) x kq(4)
    const int c0   = bid * 16;
    const int colL = tid & 15;
    const int bq   = (tid >> 4) & 7;
    const int kq   = tid >> 7;

    // ---- startup: persistent weight slice into SMEM ----
    {
        const float* Wsrc;
        int wn, cbase;
        if (bid < 128) {
            int gate = c0 >> 9;
            Wsrc = (gate == 0) ? U0 : (gate == 1) ? U1 : (gate == 2) ? U2 : U3;
            wn = 512; cbase = c0 & 511;
        } else {
            Wsrc = W1h; wn = 256; cbase = c0 - 2048;
        }
        for (int i = tid; i < 4096; i += NTH) {
            int k2 = i >> 4, cl = i & 15;
            int ch = cbase + cl;
            float e = Wsrc[(size_t)(2 * k2) * wn + ch];
            float o = Wsrc[(size_t)(2 * k2 + 1) * wn + ch];
            sW64[k2 * 16 + cl] = pk2(e, o);
        }
    }

    // P2 roles
    const bool p2act = (bid < 128);
    const int pb = bid >> 2;
    const int pq = bid & 3;
    const int chp = tid & 255;         // local col-pair (512 local cols)
    const int lh  = tid >> 8;          // l-half

    // ---- startup: register-resident ctxC slice for P2 ----
    u64 rv[32];
    {
        int lc0 = chp * 2;
        int gg = lc0 >> 7, ii = lc0 & 127;
        int gcol = gg * 512 + pq * QCH + ii;
        const float* cc = g_ctxC + ((size_t)(pb * 64 + lh * 32)) * NCOL + gcol;
        if (p2act) {
#pragma unroll
            for (int li = 0; li < 32; li++)
                rv[li] = *(const u64*)(cc + (size_t)li * NCOL);
        } else {
#pragma unroll
            for (int li = 0; li < 32; li++) rv[li] = 0;
        }
    }
    if (tid < AA) sW2s[tid] = W2[tid];

    for (int t = 0; t < TT; t++) {
        // ================= PHASE 1: unified GEMM over h =================
        if (t > 0) {
            // cross-block mutable: L2-direct reads
            const float4* src = (const float4*)g_hp;
            float4* dst = (float4*)sTp;
            for (int f4 = tid; f4 < 4096; f4 += NTH) dst[f4] = __ldcg(src + f4);
        }
        __syncthreads();

        u64 ac[4] = {0, 0, 0, 0};
        if (t > 0) {
            const u64* wp = sW64 + (kq * 64) * 16 + colL;
            const u64* hp = sTp64 + (kq * 64) * 32 + bq * 4;
#pragma unroll 8
            for (int p = 0; p < 64; p++) {
                u64 w = *wp;
                ulonglong2 ha = *(const ulonglong2*)hp;
                ulonglong2 hb = *(const ulonglong2*)(hp + 2);
                ac[0] = fma2(w, ha.x, ac[0]);
                ac[1] = fma2(w, ha.y, ac[1]);
                ac[2] = fma2(w, hb.x, ac[2]);
                ac[3] = fma2(w, hb.y, ac[3]);
                wp += 16; hp += 32;
            }
        }
#pragma unroll
        for (int bi = 0; bi < 4; bi++) {
            float2 r = upk2(ac[bi]);
            sRed[kq * 512 + (bq * 4 + bi) * 16 + colL] = r.x + r.y;
        }
        __syncthreads();
        {
            int o = tid;
            float s = sRed[o] + sRed[512 + o] + sRed[1024 + o] + sRed[1536 + o];
            int b = o >> 4, cl = o & 15;
            if (bid < 128) {
                int col = c0 + cl;
                s += g_xg[((size_t)t * BB + b) * NCOL + col];
                g_gbuf[(size_t)b * NCOL + col] = s;
            } else {
                g_attv[b * AA + (c0 - 2048) + cl] = s;
            }
        }
        gbar(bid, tid, base + (unsigned)(2 * t + 1));

        // ================= PHASE 2: per (b, quarter) block =================
        if (p2act) {
            const int b = pb;
            if (tid < AA) sAtt[tid] = __ldcg(&g_attv[b * AA + tid]);
            __syncthreads();
            // scores: warp per 4 l  (g_ctr is read-only -> stays L1-resident now)
            {
                int warp = tid >> 5, lane = tid & 31;
#pragma unroll
                for (int i = 0; i < 4; i++) {
                    int l = warp * 4 + i;
                    const float* ct = g_ctr + ((size_t)b * LL + l) * AA;
                    float p = 0.f;
#pragma unroll
                    for (int j = 0; j < 8; j++) {
                        int a = lane + j * 32;
                        p += tanh_ap(ct[a] + sAtt[a]) * sW2s[a];
                    }
#pragma unroll
                    for (int o = 16; o > 0; o >>= 1) p += __shfl_xor_sync(0xffffffffu, p, o);
                    if (lane == 0)
                        sE[l] = __expf(p + b2v) * (float)cmask[b * LL + l];
                }
            }
            __syncthreads();
            if (tid < 32) {
                float v = sE[tid] + sE[tid + 32];
#pragma unroll
                for (int o = 16; o > 0; o >>= 1) v += __shfl_xor_sync(0xffffffffu, v, o);
                if (tid == 0) sSum[0] = v;
            }
            __syncthreads();
            if (tid < 64) {
                float av = sE[tid] * __fdividef(1.0f, sSum[0]);
                sA[tid] = av;
                sApr[tid] = pk2(av, av);
            }
            __syncthreads();

            // gsum from registers (32 fma2)
            u64 acc = 0;
#pragma unroll
            for (int li = 0; li < 32; li++)
                acc = fma2(rv[li], sApr[lh * 32 + li], acc);
            if (lh == 1) sRedU[chp] = acc;

            // out_x partials (context read-only -> L1-resident)
            if (tid < 256) {
                int lg = tid >> 5, d4 = tid & 31;
                float4 xp = make_float4(0.f, 0.f, 0.f, 0.f);
                const float* cb = context + ((size_t)b * LL + lg * 8) * DD + pq * QCH + d4 * 4;
#pragma unroll
                for (int li = 0; li < 8; li++) {
                    float av = sA[lg * 8 + li];
                    float4 v = *(const float4*)(cb + (size_t)li * DD);
                    xp.x += av * v.x; xp.y += av * v.y; xp.z += av * v.z; xp.w += av * v.w;
                }
                *(float4*)&sRed[tid * 4] = xp;
            }
            __syncthreads();
            if (lh == 0) {
                u64 tot = add2(acc, sRedU[chp]);
                *(u64*)&sG[chp * 2] = tot;
            }
            if (tid < 32) {
                float4 s = make_float4(0.f, 0.f, 0.f, 0.f);
#pragma unroll
                for (int lg = 0; lg < 8; lg++) {
                    float4 v = *(const float4*)&sRed[(lg * 32 + tid) * 4];
                    s.x += v.x; s.y += v.y; s.z += v.z; s.w += v.w;
                }
                *(float4*)(out_x + ((size_t)b * TT + t) * DD + pq * QCH + tid * 4) = s;
            }
            __syncthreads();

            // fused LSTM epilogue: 64 ch-pairs
            if (tid < 64) {
                int i2 = tid;
                int ch0 = pq * QCH + i2 * 2;
                float gs[4][2];
#pragma unroll
                for (int g = 0; g < 4; g++) {
                    float2 sg = *(const float2*)&sG[(g * 64 + i2) * 2];
                    float2 gb = __ldcg((const float2*)&g_gbuf[(size_t)b * NCOL + g * 512 + ch0]);
                    gs[g][0] = sg.x + gb.x;
                    gs[g][1] = sg.y + gb.y;
                }
                // own-SM state: plain loads (write-through, same SM wrote them)
                float2 cprev = make_float2(0.f, 0.f), hprev = make_float2(0.f, 0.f);
                if (t > 0) {
                    cprev = *(const float2*)&g_cst[(size_t)b * HH + ch0];
                    hprev = *(const float2*)&g_hp[(size_t)(ch0 >> 1) * 64 + b * 2];
                }
                float m = mask[b * TT + t];
                float hn[2], cn[2];
#pragma unroll
                for (int pp = 0; pp < 2; pp++) {
                    float iv = sig_ap(gs[0][pp]);
                    float fv = sig_ap(gs[1][pp]);
                    float gv = tanh_ap(gs[2][pp]);
                    float ov = sig_ap(gs[3][pp]);
                    float cp_ = pp ? cprev.y : cprev.x;
                    float hp_ = pp ? hprev.y : hprev.x;
                    float cnew = fv * cp_ + iv * gv;
                    float hnew = ov * tanh_ap(cnew);
                    hn[pp] = (1.f - m) * hp_ + m * hnew;
                    cn[pp] = (1.f - m) * cp_ + m * cnew;
                }
                *(float2*)(out_h + ((size_t)b * TT + t) * HH + ch0) = make_float2(hn[0], hn[1]);
                *(float2*)(out_c + ((size_t)b * TT + t) * HH + ch0) = make_float2(cn[0], cn[1]);
                *(float2*)&g_cst[(size_t)b * HH + ch0] = make_float2(cn[0], cn[1]);
                *(float2*)&g_hp[(size_t)(ch0 >> 1) * 64 + b * 2] = make_float2(hn[0], hn[1]);
            }
        }
        gbar(bid, tid, base + (unsigned)(2 * t + 2));
    }

    if (bid == 0 && tid == 0)
        st_release(&g_epoch, base + (unsigned)(2 * TT));
}

// ---------------- host launcher ----------------
extern "C" void kernel_launch(void* const* d_in, const int* in_sizes, int n_in,
                              void* d_out, int out_size) {
    (void)in_sizes; (void)n_in; (void)out_size;
    const float* X    = (const float*)d_in[0];
    const float* ctx  = (const float*)d_in[1];
    const float* mask = (const float*)d_in[2];
    const int*   cm   = (const int*)d_in[3];
    const float* W[4]; const float* U[4]; const float* C[4]; const float* bi[4];
    for (int gg = 0; gg < 4; gg++) {
        W[gg]  = (const float*)d_in[4 + 4 * gg];
        U[gg]  = (const float*)d_in[5 + 4 * gg];
        C[gg]  = (const float*)d_in[6 + 4 * gg];
        bi[gg] = (const float*)d_in[7 + 4 * gg];
    }
    const float* attW1c = (const float*)d_in[20];
    const float* attW1h = (const float*)d_in[21];
    const float* attB1  = (const float*)d_in[22];
    const float* attW2  = (const float*)d_in[23];
    const float* attB2  = (const float*)d_in[24];
    float* out = (float*)d_out;

    float *xg_ptr = nullptr, *ctr_ptr = nullptr, *ctxC_ptr = nullptr, *zb_ptr = nullptr;
    cudaGetSymbolAddress((void**)&xg_ptr, g_xg);
    cudaGetSymbolAddress((void**)&ctr_ptr, g_ctr);
    cudaGetSymbolAddress((void**)&ctxC_ptr, g_ctxC);
    cudaGetSymbolAddress((void**)&zb_ptr, g_zbias);

    // xg = X@W + b : rows (t*32+b), cols 2048
    dim3 grid1(NCOL / 64, (TT * BB) / 64);
    gemm_proj<<<grid1, 256>>>(X, W[0], W[1], W[2], W[3],
                              bi[0], bi[1], bi[2], bi[3],
                              xg_ptr, NCOL, 512, 512, 1);
    // ctx_trans
    dim3 grid2(AA / 64, (BB * LL) / 64);
    gemm_proj<<<grid2, 256>>>(ctx, attW1c, attW1c, attW1c, attW1c,
                              attB1, attB1, attB1, attB1,
                              ctr_ptr, AA, AA, AA, 0);
    // ctxC = context@C
    dim3 grid3(NCOL / 64, (BB * LL) / 64);
    gemm_proj<<<grid3, 256>>>(ctx, C[0], C[1], C[2], C[3],
                              zb_ptr, zb_ptr, zb_ptr, zb_ptr,
                              ctxC_ptr, NCOL, 512, 512, 0);

    size_t smem_bytes = (size_t)SMEM_FLOATS * sizeof(float);
    static bool attr_set = false;
    if (!attr_set) {
        cudaFuncSetAttribute(recur_kernel, cudaFuncAttributeMaxDynamicSharedMemorySize,
                             (int)smem_bytes);
        attr_set = true;
    }
    recur_kernel<<<NBLK, NTH, smem_bytes>>>(ctx, mask, cm,
                                            U[0], U[1], U[2], U[3], attW1h,
                                            attW2, attB2, out);
}

// round 11
// speedup vs baseline: 1.4532x; 1.0490x over previous
#include <cuda_runtime.h>
#include <cstdint>
#include <cstddef>

#define BB 32
#define TT 128
#define LL 64
#define HH 512
#define AA 256
#define DD 512
#define NCOL 2048
#define NBLK 144
#define NTH 512

typedef unsigned long long u64;

// ---------------- device scratch ----------------
__device__ float g_xg[(size_t)TT * BB * NCOL];     // [t*32+b][col]
__device__ float g_ctr[(size_t)BB * LL * AA];      // ctx_trans [b*64+l][a]
__device__ float g_ctxC[(size_t)BB * LL * NCOL];   // context@C [b*64+l][col]
__device__ float g_attv[(size_t)BB * AA];          // [b][a]
__device__ float g_e[(size_t)LL * BB];             // raw exp scores [l][b]... stored [l*32+b]
__device__ float g_hpA[(size_t)256 * BB * 2];      // h pair buffers [k2][b]{e,o}
__device__ float g_hpB[(size_t)256 * BB * 2];
__device__ float g_zbias[512];
__device__ unsigned g_fatt[16 * 32];
__device__ unsigned g_fe[128 * 32];
__device__ unsigned g_fh[128 * 32];
__device__ unsigned g_epoch;

// ---------------- helpers ----------------
__device__ __forceinline__ u64 pk2(float lo, float hi) {
    u64 r; asm("mov.b64 %0, {%1,%2};" : "=l"(r) : "f"(lo), "f"(hi)); return r;
}
__device__ __forceinline__ float2 upk2(u64 v) {
    float2 r; asm("mov.b64 {%0,%1}, %2;" : "=f"(r.x), "=f"(r.y) : "l"(v)); return r;
}
__device__ __forceinline__ u64 fma2(u64 a, u64 b, u64 c) {
    u64 d; asm("fma.rn.f32x2 %0, %1, %2, %3;" : "=l"(d) : "l"(a), "l"(b), "l"(c)); return d;
}
__device__ __forceinline__ float tanh_ap(float x) {
    float y; asm("tanh.approx.f32 %0, %1;" : "=f"(y) : "f"(x)); return y;
}
__device__ __forceinline__ float sig_ap(float x) {
    return fmaf(tanh_ap(0.5f * x), 0.5f, 0.5f);
}
__device__ __forceinline__ void st_release(unsigned* p, unsigned v) {
    asm volatile("st.release.gpu.global.u32 [%0], %1;" :: "l"(p), "r"(v) : "memory");
}
__device__ __forceinline__ unsigned ld_acquire(const unsigned* p) {
    unsigned v;
    asm volatile("ld.acquire.gpu.global.u32 %0, [%1];" : "=r"(v) : "l"(p) : "memory");
    return v;
}

// ---------------- prologue GEMM, f32x2 inner product ----------------
__global__ void __launch_bounds__(256) gemm_proj(
    const float* __restrict__ A,
    const float* __restrict__ Wa, const float* __restrict__ Wb,
    const float* __restrict__ Wc, const float* __restrict__ Wd,
    const float* __restrict__ ba, const float* __restrict__ bbi,
    const float* __restrict__ bc, const float* __restrict__ bd,
    float* __restrict__ Out, int Ncols, int wN, int wstride, int tb_mode)
{
    __shared__ u64 As2[8][64];
    __shared__ u64 Bs2[8][64];
    int tid = threadIdx.x;
    int ntile = blockIdx.x, mtile = blockIdx.y;

    int gate = (ntile * 64) / 512;
    const float* Wsel = (gate == 0) ? Wa : (gate == 1) ? Wb : (gate == 2) ? Wc : Wd;
    const float* bsel = (gate == 0) ? ba : (gate == 1) ? bbi : (gate == 2) ? bc : bd;
    int ncolbase = (ntile * 64) % wN;

    int a_r = tid >> 2;
    int a_k = (tid & 3) * 4;
    int grow = mtile * 64 + a_r;
    const float* aptr;
    if (tb_mode) {
        int t = grow >> 5, b = grow & 31;
        aptr = A + ((size_t)(b * TT + t)) * DD;
    } else {
        aptr = A + (size_t)grow * DD;
    }
    int bl_k2 = (tid >> 4) & 7;
    int bl_n  = (tid & 15) * 4;
    bool bldr = tid < 128;

    int tx = tid & 15, ty = tid >> 4;
    u64 acc2[4][4];
#pragma unroll
    for (int i = 0; i < 4; i++)
#pragma unroll
        for (int j = 0; j < 4; j++) acc2[i][j] = 0;

    for (int k0 = 0; k0 < DD; k0 += 16) {
        float4 av = *(const float4*)(aptr + k0 + a_k);
        float4 b0, b1;
        if (bldr) {
            b0 = *(const float4*)(Wsel + (size_t)(k0 + 2 * bl_k2) * wstride + ncolbase + bl_n);
            b1 = *(const float4*)(Wsel + (size_t)(k0 + 2 * bl_k2 + 1) * wstride + ncolbase + bl_n);
        }
        __syncthreads();
        As2[(a_k >> 1)][a_r]     = pk2(av.x, av.y);
        As2[(a_k >> 1) + 1][a_r] = pk2(av.z, av.w);
        if (bldr) {
            Bs2[bl_k2][bl_n + 0] = pk2(b0.x, b1.x);
            Bs2[bl_k2][bl_n + 1] = pk2(b0.y, b1.y);
            Bs2[bl_k2][bl_n + 2] = pk2(b0.z, b1.z);
            Bs2[bl_k2][bl_n + 3] = pk2(b0.w, b1.w);
        }
        __syncthreads();
#pragma unroll
        for (int k2 = 0; k2 < 8; k2++) {
            ulonglong2 a01 = *(const ulonglong2*)&As2[k2][ty * 4];
            ulonglong2 a23 = *(const ulonglong2*)&As2[k2][ty * 4 + 2];
            ulonglong2 b01 = *(const ulonglong2*)&Bs2[k2][tx * 4];
            ulonglong2 b23 = *(const ulonglong2*)&Bs2[k2][tx * 4 + 2];
            u64 aa[4] = {a01.x, a01.y, a23.x, a23.y};
            u64 bb4[4] = {b01.x, b01.y, b23.x, b23.y};
#pragma unroll
            for (int i = 0; i < 4; i++)
#pragma unroll
                for (int j = 0; j < 4; j++) acc2[i][j] = fma2(aa[i], bb4[j], acc2[i][j]);
        }
    }
#pragma unroll
    for (int i = 0; i < 4; i++) {
        int gr = mtile * 64 + ty * 4 + i;
        float r[4];
#pragma unroll
        for (int j = 0; j < 4; j++) {
            float2 v = upk2(acc2[i][j]);
            r[j] = v.x + v.y + bsel[(ncolbase + tx * 4 + j) % wN];
        }
        *(float4*)(Out + (size_t)gr * Ncols + ntile * 64 + tx * 4) =
            make_float4(r[0], r[1], r[2], r[3]);
    }
}

// smem map (floats)
#define OFF_H    8192
#define OFF_RED  24576
#define OFF_ACC  28672
#define OFF_DOT  29184
#define OFF_E    29696
#define OFF_APR  31744
#define OFF_ATT  33792
#define OFF_A    34048
#define OFF_W2   34112
#define OFF_SUMA 34368
#define OFF_CST  34400
#define OFF_HST  34528
#define SMEM_FLOATS 34656

// ---------------- persistent recurrent kernel ----------------
__global__ void __launch_bounds__(NTH, 1) recur_kernel(
    const float* __restrict__ context,
    const float* __restrict__ mask,
    const int*   __restrict__ cmask,
    const float* __restrict__ U0, const float* __restrict__ U1,
    const float* __restrict__ U2, const float* __restrict__ U3,
    const float* __restrict__ W1h,
    const float* __restrict__ W2, const float* __restrict__ b2,
    float* __restrict__ out)
{
    extern __shared__ float smem[];
    u64*   sW64   = (u64*)smem;                    // [k2][16 cols] pairs
    float* sH     = smem + OFF_H;                  // h pairs [k2][32 b]
    u64*   sH64   = (u64*)sH;
    float* sRed   = smem + OFF_RED;                // 4096
    float* sAcc   = smem + OFF_ACC;                // 512 [ci][b]
    float* sDot   = smem + OFF_DOT;                // 512 [ci][b]
    float* sE     = smem + OFF_E;                  // 2048 [l][b]
    u64*   sApr64 = (u64*)(smem + OFF_APR);        // 1024 [l2][b]
    float* sAtt   = smem + OFF_ATT;                // 256
    float* sA     = smem + OFF_A;                  // 64 (a for own batch)
    float* sW2s   = smem + OFF_W2;                 // 256
    float* sSumA  = smem + OFF_SUMA;               // 32 (1/sum per b)
    float* sCst   = smem + OFF_CST;                // 128 local c state
    float* sHst   = smem + OFF_HST;                // 128 local h state

    const int tid = threadIdx.x;
    const int bid = blockIdx.x;
    const bool isCol = (bid < 128);
    float* out_h = out;
    float* out_c = out + (size_t)BB * TT * HH;
    float* out_x = out + (size_t)2 * BB * TT * HH;
    const float b2v = b2[0];

    unsigned base = ld_acquire(&g_epoch);

    // roles
    const int ch0 = bid * 4;          // col: channels [ch0, ch0+4), cols ci=g*4+chi
    const int ab  = bid - 128;        // att: a-col slice [ab*16, +16)
    const int pb  = bid >> 2;         // col P2: batch
    const int pq  = bid & 3;          // col P2: quarter (l-chunk + dim-chunk)

    // P1 thread roles: 2 cols x 4 b x 32 k2
    const int cp = tid & 7;
    const int bq = (tid >> 3) & 7;
    const int kq = tid >> 6;

    // ---- startup: weight slice into SMEM ----
    for (int i = tid; i < 4096; i += NTH) {
        int k2 = i >> 4, ci = i & 15;
        float e, o;
        if (isCol) {
            int g = ci >> 2, ch = ch0 + (ci & 3);
            const float* Ug = (g == 0) ? U0 : (g == 1) ? U1 : (g == 2) ? U2 : U3;
            e = Ug[(size_t)(2 * k2) * 512 + ch];
            o = Ug[(size_t)(2 * k2 + 1) * 512 + ch];
        } else {
            int a = ab * 16 + ci;
            e = W1h[(size_t)(2 * k2) * AA + a];
            o = W1h[(size_t)(2 * k2 + 1) * AA + a];
        }
        sW64[i] = pk2(e, o);
    }
    // ---- startup: register-resident ctxC (col only) ----
    u64 rv[32];
    {
        int ci = tid >> 5, b = tid & 31;
        if (isCol) {
            int col = (ci >> 2) * 512 + ch0 + (ci & 3);
            const float* cc = g_ctxC + (size_t)(b * 64) * NCOL + col;
#pragma unroll
            for (int li = 0; li < 32; li++) {
                float e = cc[(size_t)(2 * li) * NCOL];
                float o = cc[(size_t)(2 * li + 1) * NCOL];
                rv[li] = pk2(e, o);
            }
        } else {
#pragma unroll
            for (int li = 0; li < 32; li++) rv[li] = 0;
        }
    }
    if (tid < AA) sW2s[tid] = W2[tid];
    if (tid < 128) { sCst[tid] = 0.f; sHst[tid] = 0.f; }
    __syncthreads();

    for (int t = 0; t < TT; t++) {
        const unsigned gen = base + (unsigned)(t + 1);
        const float* hread = (t & 1) ? g_hpA : g_hpB;   // buf written at t-1
        float* hwrite = (t & 1) ? g_hpB : g_hpA;        // buf for h(t)

        // ===== load h broadcast (L2-direct) =====
        if (t > 0) {
            const float4* src = (const float4*)hread;
            float4* dst = (float4*)sH;
            for (int f4 = tid; f4 < 4096; f4 += NTH) dst[f4] = __ldcg(src + f4);
        }
        __syncthreads();

        // ===== P1 matvec: 2 cols x 4 b per thread =====
        u64 ac[2][4];
#pragma unroll
        for (int i = 0; i < 2; i++)
#pragma unroll
            for (int j = 0; j < 4; j++) ac[i][j] = 0;
        if (t > 0) {
            const u64* wp = sW64 + (kq * 32) * 16 + cp * 2;
            const u64* hp = sH64 + (kq * 32) * 32 + bq * 4;
#pragma unroll 8
            for (int p = 0; p < 32; p++) {
                ulonglong2 w2 = *(const ulonglong2*)wp;
                ulonglong2 ha = *(const ulonglong2*)hp;
                ulonglong2 hb = *(const ulonglong2*)(hp + 2);
                ac[0][0] = fma2(w2.x, ha.x, ac[0][0]);
                ac[0][1] = fma2(w2.x, ha.y, ac[0][1]);
                ac[0][2] = fma2(w2.x, hb.x, ac[0][2]);
                ac[0][3] = fma2(w2.x, hb.y, ac[0][3]);
                ac[1][0] = fma2(w2.y, ha.x, ac[1][0]);
                ac[1][1] = fma2(w2.y, ha.y, ac[1][1]);
                ac[1][2] = fma2(w2.y, hb.x, ac[1][2]);
                ac[1][3] = fma2(w2.y, hb.y, ac[1][3]);
                wp += 16; hp += 32;
            }
        }
#pragma unroll
        for (int bi = 0; bi < 4; bi++) {
            float2 r0 = upk2(ac[0][bi]);
            float2 r1 = upk2(ac[1][bi]);
            *(float2*)&sRed[kq * 512 + (bq * 4 + bi) * 16 + cp * 2] =
                make_float2(r0.x + r0.y, r1.x + r1.y);
        }
        __syncthreads();
        {
            float s = 0.f;
#pragma unroll
            for (int q = 0; q < 8; q++) s += sRed[q * 512 + tid];
            int b = tid >> 4, ci = tid & 15;
            if (isCol) {
                int col = (ci >> 2) * 512 + ch0 + (ci & 3);
                s += __ldcg(&g_xg[((size_t)t * BB + b) * NCOL + col]);
                sAcc[ci * 32 + b] = s;
            } else {
                g_attv[b * AA + ab * 16 + ci] = s;
            }
        }
        __syncthreads();

        if (!isCol) {
            // att block done: publish, then wait end of step
            if (tid == 0) st_release(&g_fatt[ab * 32], gen);
        } else {
            // ===== col: wait attv, distributed scores =====
            if (tid < 16) {
                while (ld_acquire(&g_fatt[tid * 32]) < gen) { }
            }
            __syncthreads();
            if (tid < AA) sAtt[tid] = __ldcg(&g_attv[pb * AA + tid]);
            __syncthreads();
            {
                int w = tid >> 5, lane = tid & 31;
                int l = pq * 16 + w;
                const float* ct = g_ctr + ((size_t)pb * LL + l) * AA;  // L1-resident
                float p = 0.f;
#pragma unroll
                for (int j = 0; j < 8; j++) {
                    int a = lane + j * 32;
                    p += tanh_ap(ct[a] + sAtt[a]) * sW2s[a];
                }
#pragma unroll
                for (int o = 16; o > 0; o >>= 1) p += __shfl_xor_sync(0xffffffffu, p, o);
                if (lane == 0)
                    g_e[l * 32 + pb] = __expf(p + b2v) * (float)cmask[pb * LL + l];
            }
            __syncthreads();
            if (tid == 0) st_release(&g_fe[bid * 32], gen);
            if (tid < 128) {
                while (ld_acquire(&g_fe[tid * 32]) < gen) { }
            }
            __syncthreads();
            // load all e [l][b]
            ((float4*)sE)[tid] = __ldcg(((const float4*)g_e) + tid);
            __syncthreads();
            if (tid < 32) {
                float s = 0.f;
#pragma unroll
                for (int i = 0; i < 64; i++) s += sE[i * 32 + tid];
                sSumA[tid] = __fdividef(1.0f, s);
            }
            __syncthreads();
            // build a-pairs [l2][b] + scalar a for own batch
            {
                for (int i = tid; i < 1024; i += NTH) {
                    int l2 = i >> 5, b = i & 31;
                    float rs = sSumA[b];
                    sApr64[i] = pk2(sE[(2 * l2) * 32 + b] * rs,
                                    sE[(2 * l2 + 1) * 32 + b] * rs);
                }
                if (tid < 64) sA[tid] = sE[tid * 32 + pb] * sSumA[pb];
            }
            __syncthreads();
            // gsum from registers
            {
                int ci = tid >> 5, b = tid & 31;
                u64 acc = 0;
#pragma unroll
                for (int li = 0; li < 32; li++)
                    acc = fma2(rv[li], sApr64[li * 32 + b], acc);
                float2 r = upk2(acc);
                sDot[ci * 32 + b] = r.x + r.y;
            }
            // out_x partials (context L1-resident slice)
            if (tid < 256) {
                int lg = tid >> 5, d4 = tid & 31;
                float4 xp = make_float4(0.f, 0.f, 0.f, 0.f);
                const float* cb = context + ((size_t)pb * LL + lg * 8) * DD + pq * 128 + d4 * 4;
#pragma unroll
                for (int li = 0; li < 8; li++) {
                    float av = sA[lg * 8 + li];
                    float4 v = *(const float4*)(cb + (size_t)li * DD);
                    xp.x += av * v.x; xp.y += av * v.y; xp.z += av * v.z; xp.w += av * v.w;
                }
                *(float4*)&sRed[tid * 4] = xp;
            }
            __syncthreads();
            if (tid < 32) {
                float4 s = make_float4(0.f, 0.f, 0.f, 0.f);
#pragma unroll
                for (int lg = 0; lg < 8; lg++) {
                    float4 v = *(const float4*)&sRed[(lg * 32 + tid) * 4];
                    s.x += v.x; s.y += v.y; s.z += v.z; s.w += v.w;
                }
                *(float4*)(out_x + ((size_t)pb * TT + t) * DD + pq * 128 + tid * 4) = s;
            }
            // fused epilogue: 64 threads, 2 ch each; state in SMEM
            if (tid < 64) {
                int b = tid & 31, j = tid >> 5;
                float m = mask[b * TT + t];
                float hn2[2], cn2[2];
#pragma unroll
                for (int pp = 0; pp < 2; pp++) {
                    int chI = 2 * j + pp;
                    float gs[4];
#pragma unroll
                    for (int g = 0; g < 4; g++) {
                        int ci = g * 4 + chI;
                        gs[g] = sAcc[ci * 32 + b] + sDot[ci * 32 + b];
                    }
                    float cprev = sCst[chI * 32 + b];
                    float hprev = sHst[chI * 32 + b];
                    float iv = sig_ap(gs[0]);
                    float fv = sig_ap(gs[1]);
                    float gv = tanh_ap(gs[2]);
                    float ov = sig_ap(gs[3]);
                    float cn = fv * cprev + iv * gv;
                    float hn = ov * tanh_ap(cn);
                    hn = (1.f - m) * hprev + m * hn;
                    cn = (1.f - m) * cprev + m * cn;
                    sCst[chI * 32 + b] = cn;
                    sHst[chI * 32 + b] = hn;
                    hn2[pp] = hn; cn2[pp] = cn;
                }
                int ch = ch0 + 2 * j;
                *(float2*)(out_h + ((size_t)b * TT + t) * HH + ch) = make_float2(hn2[0], hn2[1]);
                *(float2*)(out_c + ((size_t)b * TT + t) * HH + ch) = make_float2(cn2[0], cn2[1]);
                *(u64*)&hwrite[((size_t)(ch >> 1) * 32 + b) * 2] = pk2(hn2[0], hn2[1]);
            }
            __syncthreads();
            if (tid == 0) st_release(&g_fh[bid * 32], gen);
        }

        // ===== end-of-step barrier on col h-flags =====
        if (tid < 128) {
            while (ld_acquire(&g_fh[tid * 32]) < gen) { }
        }
        __syncthreads();
    }

    if (bid == 0 && tid == 0)
        st_release(&g_epoch, base + (unsigned)TT);
}

// ---------------- host launcher ----------------
extern "C" void kernel_launch(void* const* d_in, const int* in_sizes, int n_in,
                              void* d_out, int out_size) {
    (void)in_sizes; (void)n_in; (void)out_size;
    const float* X    = (const float*)d_in[0];
    const float* ctx  = (const float*)d_in[1];
    const float* mask = (const float*)d_in[2];
    const int*   cm   = (const int*)d_in[3];
    const float* W[4]; const float* U[4]; const float* C[4]; const float* bi[4];
    for (int gg = 0; gg < 4; gg++) {
        W[gg]  = (const float*)d_in[4 + 4 * gg];
        U[gg]  = (const float*)d_in[5 + 4 * gg];
        C[gg]  = (const float*)d_in[6 + 4 * gg];
        bi[gg] = (const float*)d_in[7 + 4 * gg];
    }
    const float* attW1c = (const float*)d_in[20];
    const float* attW1h = (const float*)d_in[21];
    const float* attB1  = (const float*)d_in[22];
    const float* attW2  = (const float*)d_in[23];
    const float* attB2  = (const float*)d_in[24];
    float* out = (float*)d_out;

    float *xg_ptr = nullptr, *ctr_ptr = nullptr, *ctxC_ptr = nullptr, *zb_ptr = nullptr;
    cudaGetSymbolAddress((void**)&xg_ptr, g_xg);
    cudaGetSymbolAddress((void**)&ctr_ptr, g_ctr);
    cudaGetSymbolAddress((void**)&ctxC_ptr, g_ctxC);
    cudaGetSymbolAddress((void**)&zb_ptr, g_zbias);

    // xg = X@W + b : rows (t*32+b), cols 2048
    dim3 grid1(NCOL / 64, (TT * BB) / 64);
    gemm_proj<<<grid1, 256>>>(X, W[0], W[1], W[2], W[3],
                              bi[0], bi[1], bi[2], bi[3],
                              xg_ptr, NCOL, 512, 512, 1);
    // ctx_trans = context@att_ctx_W1 + b1
    dim3 grid2(AA / 64, (BB * LL) / 64);
    gemm_proj<<<grid2, 256>>>(ctx, attW1c, attW1c, attW1c, attW1c,
                              attB1, attB1, attB1, attB1,
                              ctr_ptr, AA, AA, AA, 0);
    // ctxC = context@C
    dim3 grid3(NCOL / 64, (BB * LL) / 64);
    gemm_proj<<<grid3, 256>>>(ctx, C[0], C[1], C[2], C[3],
                              zb_ptr, zb_ptr, zb_ptr, zb_ptr,
                              ctxC_ptr, NCOL, 512, 512, 0);

    size_t smem_bytes = (size_t)SMEM_FLOATS * sizeof(float);
    static bool attr_set = false;
    if (!attr_set) {
        cudaFuncSetAttribute(recur_kernel, cudaFuncAttributeMaxDynamicSharedMemorySize,
                             (int)smem_bytes);
        attr_set = true;
    }
    recur_kernel<<<NBLK, NTH, smem_bytes>>>(ctx, mask, cm,
                                            U[0], U[1], U[2], U[3], attW1h,
                                            attW2, attB2, out);
}

// round 12
// speedup vs baseline: 1.5553x; 1.0703x over previous
#include <cuda_runtime.h>
#include <cstdint>
#include <cstddef>

#define BB 32
#define TT 128
#define LL 64
#define HH 512
#define AA 256
#define DD 512
#define NCOL 2048
#define NBLK 144
#define NTH 512

typedef unsigned long long u64;

// ---------------- device scratch ----------------
__device__ float g_xg[(size_t)TT * BB * NCOL];     // [t*32+b][col]
__device__ float g_ctr[(size_t)BB * LL * AA];      // ctx_trans [b*64+l][a]
__device__ float g_ctxC[(size_t)BB * LL * NCOL];   // context@C [b*64+l][col]
__device__ float g_attv[(size_t)BB * AA];          // [b][a]
__device__ float g_e[(size_t)LL * BB];             // raw exp scores [l*32+b]
__device__ float g_hpA[(size_t)256 * BB * 2];      // h pair buffers [k2][b]{e,o}
__device__ float g_hpB[(size_t)256 * BB * 2];
__device__ float g_zbias[512];
__device__ unsigned g_fatt[16 * 32];
__device__ unsigned g_fe[128 * 32];
__device__ unsigned g_fh[128 * 32];
__device__ unsigned g_epoch;

// ---------------- helpers ----------------
__device__ __forceinline__ u64 pk2(float lo, float hi) {
    u64 r; asm("mov.b64 %0, {%1,%2};" : "=l"(r) : "f"(lo), "f"(hi)); return r;
}
__device__ __forceinline__ float2 upk2(u64 v) {
    float2 r; asm("mov.b64 {%0,%1}, %2;" : "=f"(r.x), "=f"(r.y) : "l"(v)); return r;
}
__device__ __forceinline__ u64 fma2(u64 a, u64 b, u64 c) {
    u64 d; asm("fma.rn.f32x2 %0, %1, %2, %3;" : "=l"(d) : "l"(a), "l"(b), "l"(c)); return d;
}
__device__ __forceinline__ float tanh_ap(float x) {
    float y; asm("tanh.approx.f32 %0, %1;" : "=f"(y) : "f"(x)); return y;
}
__device__ __forceinline__ float sig_ap(float x) {
    return fmaf(tanh_ap(0.5f * x), 0.5f, 0.5f);
}
__device__ __forceinline__ void st_release(unsigned* p, unsigned v) {
    asm volatile("st.release.gpu.global.u32 [%0], %1;" :: "l"(p), "r"(v) : "memory");
}
__device__ __forceinline__ unsigned ld_acquire(const unsigned* p) {
    unsigned v;
    asm volatile("ld.acquire.gpu.global.u32 %0, [%1];" : "=r"(v) : "l"(p) : "memory");
    return v;
}

// ---------------- prologue GEMM: double-buffered, f32x2 inner product ----------------
__global__ void __launch_bounds__(256) gemm_proj(
    const float* __restrict__ A,
    const float* __restrict__ Wa, const float* __restrict__ Wb,
    const float* __restrict__ Wc, const float* __restrict__ Wd,
    const float* __restrict__ ba, const float* __restrict__ bbi,
    const float* __restrict__ bc, const float* __restrict__ bd,
    float* __restrict__ Out, int Ncols, int wN, int wstride, int tb_mode)
{
    __shared__ u64 As2[2][8][64];
    __shared__ u64 Bs2[2][8][64];
    int tid = threadIdx.x;
    int ntile = blockIdx.x, mtile = blockIdx.y;

    int gate = (ntile * 64) / 512;
    const float* Wsel = (gate == 0) ? Wa : (gate == 1) ? Wb : (gate == 2) ? Wc : Wd;
    const float* bsel = (gate == 0) ? ba : (gate == 1) ? bbi : (gate == 2) ? bc : bd;
    int ncolbase = (ntile * 64) % wN;

    int a_r = tid >> 2;
    int a_k = (tid & 3) * 4;
    int grow = mtile * 64 + a_r;
    const float* aptr;
    if (tb_mode) {
        int t = grow >> 5, b = grow & 31;
        aptr = A + ((size_t)(b * TT + t)) * DD;
    } else {
        aptr = A + (size_t)grow * DD;
    }
    int bl_k2 = (tid >> 4) & 7;
    int bl_n  = (tid & 15) * 4;
    bool bldr = tid < 128;

    int tx = tid & 15, ty = tid >> 4;
    u64 acc2[4][4];
#pragma unroll
    for (int i = 0; i < 4; i++)
#pragma unroll
        for (int j = 0; j < 4; j++) acc2[i][j] = 0;

    // preload k-chunk 0
    float4 av = *(const float4*)(aptr + a_k);
    float4 b0, b1;
    if (bldr) {
        b0 = *(const float4*)(Wsel + (size_t)(2 * bl_k2) * wstride + ncolbase + bl_n);
        b1 = *(const float4*)(Wsel + (size_t)(2 * bl_k2 + 1) * wstride + ncolbase + bl_n);
    }
    As2[0][(a_k >> 1)][a_r]     = pk2(av.x, av.y);
    As2[0][(a_k >> 1) + 1][a_r] = pk2(av.z, av.w);
    if (bldr) {
        Bs2[0][bl_k2][bl_n + 0] = pk2(b0.x, b1.x);
        Bs2[0][bl_k2][bl_n + 1] = pk2(b0.y, b1.y);
        Bs2[0][bl_k2][bl_n + 2] = pk2(b0.z, b1.z);
        Bs2[0][bl_k2][bl_n + 3] = pk2(b0.w, b1.w);
    }
    __syncthreads();

    const int NIT = DD / 16;   // 32
    for (int it = 0; it < NIT; it++) {
        int buf = it & 1;
        // prefetch next chunk while computing this one
        float4 av_n, b0_n, b1_n;
        if (it + 1 < NIT) {
            int k0 = (it + 1) * 16;
            av_n = *(const float4*)(aptr + k0 + a_k);
            if (bldr) {
                b0_n = *(const float4*)(Wsel + (size_t)(k0 + 2 * bl_k2) * wstride + ncolbase + bl_n);
                b1_n = *(const float4*)(Wsel + (size_t)(k0 + 2 * bl_k2 + 1) * wstride + ncolbase + bl_n);
            }
        }
#pragma unroll
        for (int k2 = 0; k2 < 8; k2++) {
            ulonglong2 a01 = *(const ulonglong2*)&As2[buf][k2][ty * 4];
            ulonglong2 a23 = *(const ulonglong2*)&As2[buf][k2][ty * 4 + 2];
            ulonglong2 b01 = *(const ulonglong2*)&Bs2[buf][k2][tx * 4];
            ulonglong2 b23 = *(const ulonglong2*)&Bs2[buf][k2][tx * 4 + 2];
            u64 aa[4] = {a01.x, a01.y, a23.x, a23.y};
            u64 bb4[4] = {b01.x, b01.y, b23.x, b23.y};
#pragma unroll
            for (int i = 0; i < 4; i++)
#pragma unroll
                for (int j = 0; j < 4; j++) acc2[i][j] = fma2(aa[i], bb4[j], acc2[i][j]);
        }
        if (it + 1 < NIT) {
            int nb = (it + 1) & 1;
            __syncthreads();
            As2[nb][(a_k >> 1)][a_r]     = pk2(av_n.x, av_n.y);
            As2[nb][(a_k >> 1) + 1][a_r] = pk2(av_n.z, av_n.w);
            if (bldr) {
                Bs2[nb][bl_k2][bl_n + 0] = pk2(b0_n.x, b1_n.x);
                Bs2[nb][bl_k2][bl_n + 1] = pk2(b0_n.y, b1_n.y);
                Bs2[nb][bl_k2][bl_n + 2] = pk2(b0_n.z, b1_n.z);
                Bs2[nb][bl_k2][bl_n + 3] = pk2(b0_n.w, b1_n.w);
            }
            __syncthreads();
        }
    }
#pragma unroll
    for (int i = 0; i < 4; i++) {
        int gr = mtile * 64 + ty * 4 + i;
        float r[4];
#pragma unroll
        for (int j = 0; j < 4; j++) {
            float2 v = upk2(acc2[i][j]);
            r[j] = v.x + v.y + bsel[(ncolbase + tx * 4 + j) % wN];
        }
        *(float4*)(Out + (size_t)gr * Ncols + ntile * 64 + tx * 4) =
            make_float4(r[0], r[1], r[2], r[3]);
    }
}

// smem map (floats)
#define OFF_H    8192
#define OFF_RED  24576
#define OFF_ACC  28672
#define OFF_DOT  29184
#define OFF_E    29696
#define OFF_APR  31744
#define OFF_ATT  33792
#define OFF_A    34048
#define OFF_W2   34112
#define OFF_SUMA 34368
#define OFF_CST  34400
#define OFF_HST  34528
#define SMEM_FLOATS 34656

// ---------------- persistent recurrent kernel ----------------
__global__ void __launch_bounds__(NTH, 1) recur_kernel(
    const float* __restrict__ context,
    const float* __restrict__ mask,
    const int*   __restrict__ cmask,
    const float* __restrict__ U0, const float* __restrict__ U1,
    const float* __restrict__ U2, const float* __restrict__ U3,
    const float* __restrict__ W1h,
    const float* __restrict__ W2, const float* __restrict__ b2,
    float* __restrict__ out)
{
    extern __shared__ float smem[];
    u64*   sW64   = (u64*)smem;                    // [k2][16 cols] pairs
    float* sH     = smem + OFF_H;                  // h pairs [k2][32 b]
    u64*   sH64   = (u64*)sH;
    float* sRed   = smem + OFF_RED;                // 4096
    float* sAcc   = smem + OFF_ACC;                // 512 [ci][b]
    float* sDot   = smem + OFF_DOT;                // 512 [ci][b]
    float* sE     = smem + OFF_E;                  // 2048 [l][b]
    u64*   sApr64 = (u64*)(smem + OFF_APR);        // 1024 [l2][b]
    float* sAtt   = smem + OFF_ATT;                // 256
    float* sA     = smem + OFF_A;                  // 64
    float* sW2s   = smem + OFF_W2;                 // 256
    float* sSumA  = smem + OFF_SUMA;               // 32
    float* sCst   = smem + OFF_CST;                // 128
    float* sHst   = smem + OFF_HST;                // 128

    const int tid = threadIdx.x;
    const int bid = blockIdx.x;
    const bool isCol = (bid < 128);
    float* out_h = out;
    float* out_c = out + (size_t)BB * TT * HH;
    float* out_x = out + (size_t)2 * BB * TT * HH;
    const float b2v = b2[0];

    unsigned base = ld_acquire(&g_epoch);

    // roles
    const int ch0 = bid * 4;
    const int ab  = bid - 128;
    const int pb  = bid >> 2;
    const int pq  = bid & 3;

    // P1 thread roles: 2 cols x 4 b x 32 k2
    const int cp = tid & 7;
    const int bq = (tid >> 3) & 7;
    const int kq = tid >> 6;

    // ---- startup: weight slice into SMEM ----
    for (int i = tid; i < 4096; i += NTH) {
        int k2 = i >> 4, ci = i & 15;
        float e, o;
        if (isCol) {
            int g = ci >> 2, ch = ch0 + (ci & 3);
            const float* Ug = (g == 0) ? U0 : (g == 1) ? U1 : (g == 2) ? U2 : U3;
            e = Ug[(size_t)(2 * k2) * 512 + ch];
            o = Ug[(size_t)(2 * k2 + 1) * 512 + ch];
        } else {
            int a = ab * 16 + ci;
            e = W1h[(size_t)(2 * k2) * AA + a];
            o = W1h[(size_t)(2 * k2 + 1) * AA + a];
        }
        sW64[i] = pk2(e, o);
    }
    // ---- startup: register-resident ctxC (col only) ----
    u64 rv[32];
    {
        int ci = tid >> 5, b = tid & 31;
        if (isCol) {
            int col = (ci >> 2) * 512 + ch0 + (ci & 3);
            const float* cc = g_ctxC + (size_t)(b * 64) * NCOL + col;
#pragma unroll
            for (int li = 0; li < 32; li++) {
                float e = cc[(size_t)(2 * li) * NCOL];
                float o = cc[(size_t)(2 * li + 1) * NCOL];
                rv[li] = pk2(e, o);
            }
        } else {
#pragma unroll
            for (int li = 0; li < 32; li++) rv[li] = 0;
        }
    }
    if (tid < AA) sW2s[tid] = W2[tid];
    if (tid < 128) { sCst[tid] = 0.f; sHst[tid] = 0.f; }
    __syncthreads();

    for (int t = 0; t < TT; t++) {
        const unsigned gen = base + (unsigned)(t + 1);
        const float* hread = (t & 1) ? g_hpA : g_hpB;
        float* hwrite = (t & 1) ? g_hpB : g_hpA;

        // ===== prefetch xg early (hides L2 latency behind P1) =====
        float xgpre = 0.f;
        if (isCol) {
            int b = tid >> 4, ci = tid & 15;
            int col = (ci >> 2) * 512 + ch0 + (ci & 3);
            xgpre = __ldcg(&g_xg[((size_t)t * BB + b) * NCOL + col]);
        }

        // ===== load h broadcast (L2-direct) =====
        if (t > 0) {
            const float4* src = (const float4*)hread;
            float4* dst = (float4*)sH;
            for (int f4 = tid; f4 < 4096; f4 += NTH) dst[f4] = __ldcg(src + f4);
        }
        __syncthreads();

        // ===== P1 matvec: 2 cols x 4 b per thread =====
        u64 ac[2][4];
#pragma unroll
        for (int i = 0; i < 2; i++)
#pragma unroll
            for (int j = 0; j < 4; j++) ac[i][j] = 0;
        if (t > 0) {
            const u64* wp = sW64 + (kq * 32) * 16 + cp * 2;
            const u64* hp = sH64 + (kq * 32) * 32 + bq * 4;
#pragma unroll 8
            for (int p = 0; p < 32; p++) {
                ulonglong2 w2 = *(const ulonglong2*)wp;
                ulonglong2 ha = *(const ulonglong2*)hp;
                ulonglong2 hb = *(const ulonglong2*)(hp + 2);
                ac[0][0] = fma2(w2.x, ha.x, ac[0][0]);
                ac[0][1] = fma2(w2.x, ha.y, ac[0][1]);
                ac[0][2] = fma2(w2.x, hb.x, ac[0][2]);
                ac[0][3] = fma2(w2.x, hb.y, ac[0][3]);
                ac[1][0] = fma2(w2.y, ha.x, ac[1][0]);
                ac[1][1] = fma2(w2.y, ha.y, ac[1][1]);
                ac[1][2] = fma2(w2.y, hb.x, ac[1][2]);
                ac[1][3] = fma2(w2.y, hb.y, ac[1][3]);
                wp += 16; hp += 32;
            }
        }
#pragma unroll
        for (int bi = 0; bi < 4; bi++) {
            float2 r0 = upk2(ac[0][bi]);
            float2 r1 = upk2(ac[1][bi]);
            *(float2*)&sRed[kq * 512 + (bq * 4 + bi) * 16 + cp * 2] =
                make_float2(r0.x + r0.y, r1.x + r1.y);
        }
        __syncthreads();
        {
            float s = 0.f;
#pragma unroll
            for (int q = 0; q < 8; q++) s += sRed[q * 512 + tid];
            int b = tid >> 4, ci = tid & 15;
            if (isCol) {
                sAcc[ci * 32 + b] = s + xgpre;
            } else {
                g_attv[b * AA + ab * 16 + ci] = s;
            }
        }
        __syncthreads();

        if (!isCol) {
            if (tid == 0) st_release(&g_fatt[ab * 32], gen);
        } else {
            // ===== col: wait attv, distributed scores =====
            if (tid < 16) {
                while (ld_acquire(&g_fatt[tid * 32]) < gen) { }
            }
            __syncthreads();
            if (tid < AA) sAtt[tid] = __ldcg(&g_attv[pb * AA + tid]);
            __syncthreads();
            {
                int w = tid >> 5, lane = tid & 31;
                int l = pq * 16 + w;
                const float* ct = g_ctr + ((size_t)pb * LL + l) * AA;  // L1-resident
                float p = 0.f;
#pragma unroll
                for (int j = 0; j < 8; j++) {
                    int a = lane + j * 32;
                    p += tanh_ap(ct[a] + sAtt[a]) * sW2s[a];
                }
#pragma unroll
                for (int o = 16; o > 0; o >>= 1) p += __shfl_xor_sync(0xffffffffu, p, o);
                if (lane == 0)
                    g_e[l * 32 + pb] = __expf(p + b2v) * (float)cmask[pb * LL + l];
            }
            __syncthreads();
            if (tid == 0) st_release(&g_fe[bid * 32], gen);
            if (tid < 128) {
                while (ld_acquire(&g_fe[tid * 32]) < gen) { }
            }
            __syncthreads();
            // load all e [l][b]
            ((float4*)sE)[tid] = __ldcg(((const float4*)g_e) + tid);
            __syncthreads();
            if (tid < 32) {
                float s = 0.f;
#pragma unroll
                for (int i = 0; i < 64; i++) s += sE[i * 32 + tid];
                sSumA[tid] = __fdividef(1.0f, s);
            }
            __syncthreads();
            // a-pairs [l2][b] + scalar a for own batch
            {
                for (int i = tid; i < 1024; i += NTH) {
                    int l2 = i >> 5, b = i & 31;
                    float rs = sSumA[b];
                    sApr64[i] = pk2(sE[(2 * l2) * 32 + b] * rs,
                                    sE[(2 * l2 + 1) * 32 + b] * rs);
                }
                if (tid < 64) sA[tid] = sE[tid * 32 + pb] * sSumA[pb];
            }
            __syncthreads();
            // gsum from registers
            {
                int ci = tid >> 5, b = tid & 31;
                u64 acc = 0;
#pragma unroll
                for (int li = 0; li < 32; li++)
                    acc = fma2(rv[li], sApr64[li * 32 + b], acc);
                float2 r = upk2(acc);
                sDot[ci * 32 + b] = r.x + r.y;
            }
            __syncthreads();
            // ===== fused epilogue FIRST (h publication is the critical path) =====
            if (tid < 64) {
                int b = tid & 31, j = tid >> 5;
                float m = mask[b * TT + t];
                float hn2[2], cn2[2];
#pragma unroll
                for (int pp = 0; pp < 2; pp++) {
                    int chI = 2 * j + pp;
                    float gs[4];
#pragma unroll
                    for (int g = 0; g < 4; g++) {
                        int ci = g * 4 + chI;
                        gs[g] = sAcc[ci * 32 + b] + sDot[ci * 32 + b];
                    }
                    float cprev = sCst[chI * 32 + b];
                    float hprev = sHst[chI * 32 + b];
                    float iv = sig_ap(gs[0]);
                    float fv = sig_ap(gs[1]);
                    float gv = tanh_ap(gs[2]);
                    float ov = sig_ap(gs[3]);
                    float cn = fv * cprev + iv * gv;
                    float hn = ov * tanh_ap(cn);
                    hn = (1.f - m) * hprev + m * hn;
                    cn = (1.f - m) * cprev + m * cn;
                    sCst[chI * 32 + b] = cn;
                    sHst[chI * 32 + b] = hn;
                    hn2[pp] = hn; cn2[pp] = cn;
                }
                int ch = ch0 + 2 * j;
                *(float2*)(out_h + ((size_t)b * TT + t) * HH + ch) = make_float2(hn2[0], hn2[1]);
                *(float2*)(out_c + ((size_t)b * TT + t) * HH + ch) = make_float2(cn2[0], cn2[1]);
                *(u64*)&hwrite[((size_t)(ch >> 1) * 32 + b) * 2] = pk2(hn2[0], hn2[1]);
            }
            __syncthreads();
            if (tid == 0) st_release(&g_fh[bid * 32], gen);
            // ===== out_x off the critical path =====
            if (tid < 256) {
                int lg = tid >> 5, d4 = tid & 31;
                float4 xp = make_float4(0.f, 0.f, 0.f, 0.f);
                const float* cb = context + ((size_t)pb * LL + lg * 8) * DD + pq * 128 + d4 * 4;
#pragma unroll
                for (int li = 0; li < 8; li++) {
                    float av = sA[lg * 8 + li];
                    float4 v = *(const float4*)(cb + (size_t)li * DD);
                    xp.x += av * v.x; xp.y += av * v.y; xp.z += av * v.z; xp.w += av * v.w;
                }
                *(float4*)&sRed[tid * 4] = xp;
            }
            __syncthreads();
            if (tid < 32) {
                float4 s = make_float4(0.f, 0.f, 0.f, 0.f);
#pragma unroll
                for (int lg = 0; lg < 8; lg++) {
                    float4 v = *(const float4*)&sRed[(lg * 32 + tid) * 4];
                    s.x += v.x; s.y += v.y; s.z += v.z; s.w += v.w;
                }
                *(float4*)(out_x + ((size_t)pb * TT + t) * DD + pq * 128 + tid * 4) = s;
            }
        }

        // ===== end-of-step barrier on col h-flags =====
        if (tid < 128) {
            while (ld_acquire(&g_fh[tid * 32]) < gen) { }
        }
        __syncthreads();
    }

    if (bid == 0 && tid == 0)
        st_release(&g_epoch, base + (unsigned)TT);
}

// ---------------- host launcher ----------------
extern "C" void kernel_launch(void* const* d_in, const int* in_sizes, int n_in,
                              void* d_out, int out_size) {
    (void)in_sizes; (void)n_in; (void)out_size;
    const float* X    = (const float*)d_in[0];
    const float* ctx  = (const float*)d_in[1];
    const float* mask = (const float*)d_in[2];
    const int*   cm   = (const int*)d_in[3];
    const float* W[4]; const float* U[4]; const float* C[4]; const float* bi[4];
    for (int gg = 0; gg < 4; gg++) {
        W[gg]  = (const float*)d_in[4 + 4 * gg];
        U[gg]  = (const float*)d_in[5 + 4 * gg];
        C[gg]  = (const float*)d_in[6 + 4 * gg];
        bi[gg] = (const float*)d_in[7 + 4 * gg];
    }
    const float* attW1c = (const float*)d_in[20];
    const float* attW1h = (const float*)d_in[21];
    const float* attB1  = (const float*)d_in[22];
    const float* attW2  = (const float*)d_in[23];
    const float* attB2  = (const float*)d_in[24];
    float* out = (float*)d_out;

    float *xg_ptr = nullptr, *ctr_ptr = nullptr, *ctxC_ptr = nullptr, *zb_ptr = nullptr;
    cudaGetSymbolAddress((void**)&xg_ptr, g_xg);
    cudaGetSymbolAddress((void**)&ctr_ptr, g_ctr);
    cudaGetSymbolAddress((void**)&ctxC_ptr, g_ctxC);
    cudaGetSymbolAddress((void**)&zb_ptr, g_zbias);

    // xg = X@W + b : rows (t*32+b), cols 2048
    dim3 grid1(NCOL / 64, (TT * BB) / 64);
    gemm_proj<<<grid1, 256>>>(X, W[0], W[1], W[2], W[3],
                              bi[0], bi[1], bi[2], bi[3],
                              xg_ptr, NCOL, 512, 512, 1);
    // ctx_trans = context@att_ctx_W1 + b1
    dim3 grid2(AA / 64, (BB * LL) / 64);
    gemm_proj<<<grid2, 256>>>(ctx, attW1c, attW1c, attW1c, attW1c,
                              attB1, attB1, attB1, attB1,
                              ctr_ptr, AA, AA, AA, 0);
    // ctxC = context@C
    dim3 grid3(NCOL / 64, (BB * LL) / 64);
    gemm_proj<<<grid3, 256>>>(ctx, C[0], C[1], C[2], C[3],
                              zb_ptr, zb_ptr, zb_ptr, zb_ptr,
                              ctxC_ptr, NCOL, 512, 512, 0);

    size_t smem_bytes = (size_t)SMEM_FLOATS * sizeof(float);
    static bool attr_set = false;
    if (!attr_set) {
        cudaFuncSetAttribute(recur_kernel, cudaFuncAttributeMaxDynamicSharedMemorySize,
                             (int)smem_bytes);
        attr_set = true;
    }
    recur_kernel<<<NBLK, NTH, smem_bytes>>>(ctx, mask, cm,
                                            U[0], U[1], U[2], U[3], attW1h,
                                            attW2, attB2, out);
}